// round 12
// baseline (speedup 1.0000x reference)
#include <cuda_runtime.h>
#include <cuda_fp16.h>
#include <math.h>

#define T     1024
#define HDIM  1024
#define NEXP  16
#define IDIM  512
#define ISDIM 2048
#define TOPK  4
#define SSH   40        // smem row stride in HALFS (80B rows)

// ---------------- scratch --------------------------------------------------
__device__ int   g_counts[NEXP];
__device__ int   g_tok[NEXP * T];
__device__ float g_wt[NEXP * T];
__device__ int   g_slot[T * TOPK];
__device__ float g_sg[T];
__device__ float g_act[(size_t)NEXP * T * IDIM];
__device__ float g_acts[(size_t)T * ISDIM];
__device__ float g_down[(size_t)NEXP * T * HDIM];

// ---------------- helpers --------------------------------------------------
__device__ __forceinline__ unsigned pk(float a, float b) {
    __half2 h = __floats2half2_rn(a, b);    // a -> low half (k even), b -> high
    return *(unsigned*)&h;
}
__device__ __forceinline__ unsigned smem_u32(const void* p) {
    return (unsigned)__cvta_generic_to_shared(p);
}
__device__ __forceinline__ void ldsm4(unsigned* d, unsigned addr) {
    asm volatile("ldmatrix.sync.aligned.m8n8.x4.shared.b16 {%0,%1,%2,%3}, [%4];"
                 : "=r"(d[0]), "=r"(d[1]), "=r"(d[2]), "=r"(d[3]) : "r"(addr));
}
__device__ __forceinline__ void mma_f16(float* d, const unsigned* a, const unsigned* b) {
    asm volatile(
        "mma.sync.aligned.m16n8k16.row.col.f32.f16.f16.f32 "
        "{%0,%1,%2,%3}, {%4,%5,%6,%7}, {%8,%9}, {%0,%1,%2,%3};\n"
        : "+f"(d[0]), "+f"(d[1]), "+f"(d[2]), "+f"(d[3])
        : "r"(a[0]), "r"(a[1]), "r"(a[2]), "r"(a[3]), "r"(b[0]), "r"(b[1]));
}
__device__ __forceinline__ float silu(float g) { return g / (1.f + expf(-g)); }

// ---------------- kernel 0: zero counts -------------------------------------
__global__ void zero_counts_kernel() {
    if (threadIdx.x < NEXP) g_counts[threadIdx.x] = 0;
}

// ---------------- kernel 1: router ------------------------------------------
__global__ void router_kernel(const float* __restrict__ x,
                              const float* __restrict__ wr,
                              const float* __restrict__ wsg,
                              float* __restrict__ logits_out) {
    int t    = blockIdx.x;
    int warp = threadIdx.x >> 5;
    int lane = threadIdx.x & 31;
    __shared__ float s_logit[NEXP];

    const float* xr = x + (size_t)t * HDIM;
    {
        float acc = 0.f;
        for (int h = lane; h < HDIM; h += 32)
            acc += xr[h] * wr[h * NEXP + warp];
        #pragma unroll
        for (int o = 16; o; o >>= 1) acc += __shfl_xor_sync(0xffffffffu, acc, o);
        if (lane == 0) { s_logit[warp] = acc; logits_out[t * NEXP + warp] = acc; }
    }
    if (warp == 0) {
        float acc = 0.f;
        for (int h = lane; h < HDIM; h += 32) acc += xr[h] * wsg[h];
        #pragma unroll
        for (int o = 16; o; o >>= 1) acc += __shfl_xor_sync(0xffffffffu, acc, o);
        if (lane == 0) g_sg[t] = 1.f / (1.f + expf(-acc));
    }
    __syncthreads();

    if (threadIdx.x == 0) {
        float p[NEXP];
        float mx = -1e30f;
        #pragma unroll
        for (int e = 0; e < NEXP; e++) mx = fmaxf(mx, s_logit[e]);
        float sum = 0.f;
        #pragma unroll
        for (int e = 0; e < NEXP; e++) { p[e] = expf(s_logit[e] - mx); sum += p[e]; }
        float inv = 1.f / sum;
        #pragma unroll
        for (int e = 0; e < NEXP; e++) p[e] *= inv;

        int idx[TOPK]; float w[TOPK]; float wsum = 0.f;
        #pragma unroll
        for (int k = 0; k < TOPK; k++) {
            int best = 0; float bv = -1.f;
            #pragma unroll
            for (int e = 0; e < NEXP; e++)
                if (p[e] > bv) { bv = p[e]; best = e; }
            idx[k] = best; w[k] = bv; wsum += bv; p[best] = -2.f;
        }
        float winv = 1.f / wsum;
        #pragma unroll
        for (int k = 0; k < TOPK; k++) {
            int e = idx[k];
            int pos = atomicAdd(&g_counts[e], 1);
            g_tok[e * T + pos] = t;
            g_wt[e * T + pos]  = w[k] * winv;
            g_slot[t * TOPK + k] = e * T + pos;
        }
    }
}

// ============================================================================
// gate/up body: BM=64, BN=64, BK=16, 128 thr, warps 2x2 (warp 32x32).
// fp16 m16n8k16; fp32 loads packed to half2 at LOAD time (12 staging regs).
// ============================================================================
template<int LDB>
__device__ __forceinline__
void gateup_body(__half* sm, const float* __restrict__ Bgp,
                 const float* __restrict__ Bup,
                 const float* __restrict__ arow0,
                 int count_lim, int m0, int n0, float* __restrict__ Cout) {
    __half* As  = sm;
    __half* Btg = sm + 2 * 64 * SSH;
    __half* Btu = sm + 4 * 64 * SSH;

    int tid = threadIdx.x, lane = tid & 31, warp = tid >> 5;
    int wm = (warp >> 1) * 32, wn = (warp & 1) * 32;
    int r = lane >> 2, c = lane & 3;

    int aoff = (wm + (lane & 7) + ((lane >> 3) & 1) * 8) * SSH + ((lane >> 4) & 1) * 8;
    unsigned aA0 = smem_u32(As) + (unsigned)aoff * 2;
    int boff0 = (wn + (lane & 7) + ((lane >> 4) & 1) * 8) * SSH + ((lane >> 3) & 1) * 8;
    unsigned aBg0 = smem_u32(Btg) + (unsigned)boff0 * 2;
    unsigned aBu0 = smem_u32(Btu) + (unsigned)boff0 * 2;
    const unsigned BUFB = 64 * SSH * 2;

    int arl = tid & 63, akf = (tid >> 6) * 8;
    int bnl = tid & 63, bkf = (tid >> 6) * 8;

    unsigned sa[4], sg[4], su[4];                     // packed staging
    #define GUX_LD(K0) do {                                                    \
        float4 a0 = *(const float4*)(arow0 + (K0) + akf);                      \
        float4 a1 = *(const float4*)(arow0 + (K0) + akf + 4);                  \
        sa[0] = pk(a0.x, a0.y); sa[1] = pk(a0.z, a0.w);                        \
        sa[2] = pk(a1.x, a1.y); sa[3] = pk(a1.z, a1.w);                        \
        _Pragma("unroll")                                                      \
        for (int j = 0; j < 4; j++) {                                          \
            float g0 = Bgp[(size_t)((K0) + bkf + 2*j)     * LDB + n0 + bnl];   \
            float g1 = Bgp[(size_t)((K0) + bkf + 2*j + 1) * LDB + n0 + bnl];   \
            sg[j] = pk(g0, g1);                                                \
            float u0 = Bup[(size_t)((K0) + bkf + 2*j)     * LDB + n0 + bnl];   \
            float u1 = Bup[(size_t)((K0) + bkf + 2*j + 1) * LDB + n0 + bnl];   \
            su[j] = pk(u0, u1);                                                \
        }                                                                      \
    } while (0)
    #define GUX_ST(B) do {                                                     \
        *(uint4*)&As [(B) * 64 * SSH + arl * SSH + akf] = *(uint4*)sa;         \
        *(uint4*)&Btg[(B) * 64 * SSH + bnl * SSH + bkf] = *(uint4*)sg;         \
        *(uint4*)&Btu[(B) * 64 * SSH + bnl * SSH + bkf] = *(uint4*)su;         \
    } while (0)

    float ag[2][4][4] = {};
    float au[2][4][4] = {};

    GUX_LD(0); GUX_ST(0);
    const int NTILES = HDIM / 16;
    for (int kt = 0; kt < NTILES; kt++) {
        __syncthreads();
        if (kt + 1 < NTILES) GUX_LD((kt + 1) * 16);
        unsigned bsel = (kt & 1) * BUFB;
        {
            unsigned af[2][4], bgf[2][4], buf_[2][4];
            ldsm4(af[0], aA0 + bsel);
            ldsm4(af[1], aA0 + bsel + 16 * SSH * 2);
            ldsm4(bgf[0], aBg0 + bsel);
            ldsm4(bgf[1], aBg0 + bsel + 16 * SSH * 2);
            ldsm4(buf_[0], aBu0 + bsel);
            ldsm4(buf_[1], aBu0 + bsel + 16 * SSH * 2);
            #pragma unroll
            for (int nt = 0; nt < 4; nt++) {
                const unsigned* bg = &bgf[nt >> 1][(nt & 1) * 2];
                const unsigned* bu = &buf_[nt >> 1][(nt & 1) * 2];
                #pragma unroll
                for (int mt = 0; mt < 2; mt++) {
                    mma_f16(ag[mt][nt], af[mt], bg);
                    mma_f16(au[mt][nt], af[mt], bu);
                }
            }
        }
        if (kt + 1 < NTILES) GUX_ST((kt + 1) & 1);
    }

    #pragma unroll
    for (int mt = 0; mt < 2; mt++) {
        int row0 = m0 + wm + mt * 16 + r;
        #pragma unroll
        for (int nt = 0; nt < 4; nt++) {
            int col = n0 + wn + nt * 8 + c * 2;
            if (row0 < count_lim) {
                float2 o = { silu(ag[mt][nt][0]) * au[mt][nt][0],
                             silu(ag[mt][nt][1]) * au[mt][nt][1] };
                *(float2*)(Cout + (size_t)row0 * LDB + col) = o;
            }
            if (row0 + 8 < count_lim) {
                float2 o = { silu(ag[mt][nt][2]) * au[mt][nt][2],
                             silu(ag[mt][nt][3]) * au[mt][nt][3] };
                *(float2*)(Cout + (size_t)(row0 + 8) * LDB + col) = o;
            }
        }
    }
}

__global__ __launch_bounds__(128, 5)
void gateup_expert_tc(const float* __restrict__ x,
                      const float* __restrict__ wg,
                      const float* __restrict__ wu) {
    __shared__ __align__(16) __half sm[6 * 64 * SSH];
    int e     = blockIdx.z;
    int count = g_counts[e];
    int m0    = blockIdx.y * 64;
    if (m0 >= count) return;
    int row = m0 + (threadIdx.x & 63);
    int tok = (row < count) ? g_tok[e * T + row] : 0;   // guarded at store
    gateup_body<IDIM>(sm, wg + (size_t)e * HDIM * IDIM,
                      wu + (size_t)e * HDIM * IDIM,
                      x + (size_t)tok * HDIM, count, m0, blockIdx.x * 64,
                      g_act + (size_t)e * T * IDIM);
}

__global__ __launch_bounds__(128, 5)
void gateup_shared_tc(const float* __restrict__ x,
                      const float* __restrict__ wsg,
                      const float* __restrict__ wsu) {
    __shared__ __align__(16) __half sm[6 * 64 * SSH];
    int m0 = blockIdx.y * 64;
    gateup_body<ISDIM>(sm, wsg, wsu,
                       x + (size_t)(m0 + (threadIdx.x & 63)) * HDIM,
                       T, m0, blockIdx.x * 64, g_acts);
}

// ============================================================================
// down body: BM=64, BN=128, BK=16, 128 thr, warps 2x2 (warp 32x64).
// ============================================================================
template<int KDIM>
__device__ __forceinline__
void down_body(__half* sm, const float* __restrict__ arow0,
               const float* __restrict__ Bp, int n0, float acc[2][8][4]) {
    __half* As = sm;
    __half* Bt = sm + 2 * 64 * SSH;

    int tid = threadIdx.x, lane = tid & 31, warp = tid >> 5;
    int wm = (warp >> 1) * 32, wn = (warp & 1) * 64;

    int aoff = (wm + (lane & 7) + ((lane >> 3) & 1) * 8) * SSH + ((lane >> 4) & 1) * 8;
    unsigned aA0 = smem_u32(As) + (unsigned)aoff * 2;
    int boff0 = (wn + (lane & 7) + ((lane >> 4) & 1) * 8) * SSH + ((lane >> 3) & 1) * 8;
    unsigned aB0 = smem_u32(Bt) + (unsigned)boff0 * 2;
    const unsigned ABUF = 64 * SSH * 2, BBUF = 128 * SSH * 2;

    int arl = tid & 63, akf = (tid >> 6) * 8;
    int bnl = tid;                                      // n = 0..127, all 16 k's

    unsigned sa[4], sb[8];
    #define DNX_LD(K0) do {                                                    \
        float4 a0 = *(const float4*)(arow0 + (K0) + akf);                      \
        float4 a1 = *(const float4*)(arow0 + (K0) + akf + 4);                  \
        sa[0] = pk(a0.x, a0.y); sa[1] = pk(a0.z, a0.w);                        \
        sa[2] = pk(a1.x, a1.y); sa[3] = pk(a1.z, a1.w);                        \
        _Pragma("unroll")                                                      \
        for (int j = 0; j < 8; j++) {                                          \
            float b0 = Bp[(size_t)((K0) + 2*j)     * HDIM + n0 + bnl];         \
            float b1 = Bp[(size_t)((K0) + 2*j + 1) * HDIM + n0 + bnl];         \
            sb[j] = pk(b0, b1);                                                \
        }                                                                      \
    } while (0)
    #define DNX_ST(B) do {                                                     \
        *(uint4*)&As[(B) * 64 * SSH + arl * SSH + akf]   = *(uint4*)sa;        \
        *(uint4*)&Bt[(B) * 128 * SSH + bnl * SSH]        = *(uint4*)sb;        \
        *(uint4*)&Bt[(B) * 128 * SSH + bnl * SSH + 8]    = *(uint4*)(sb + 4);  \
    } while (0)

    DNX_LD(0); DNX_ST(0);
    const int NTILES = KDIM / 16;
    for (int kt = 0; kt < NTILES; kt++) {
        __syncthreads();
        if (kt + 1 < NTILES) DNX_LD((kt + 1) * 16);
        unsigned bselA = (kt & 1) * ABUF, bselB = (kt & 1) * BBUF;
        {
            unsigned af[2][4], bf[4][4];
            ldsm4(af[0], aA0 + bselA);
            ldsm4(af[1], aA0 + bselA + 16 * SSH * 2);
            #pragma unroll
            for (int p = 0; p < 4; p++)
                ldsm4(bf[p], aB0 + bselB + p * 16 * SSH * 2);
            #pragma unroll
            for (int nt = 0; nt < 8; nt++) {
                const unsigned* b = &bf[nt >> 1][(nt & 1) * 2];
                #pragma unroll
                for (int mt = 0; mt < 2; mt++)
                    mma_f16(acc[mt][nt], af[mt], b);
            }
        }
        if (kt + 1 < NTILES) DNX_ST((kt + 1) & 1);
    }
}

__global__ __launch_bounds__(128, 5)
void down_expert_tc(const float* __restrict__ wd) {
    __shared__ __align__(16) __half sm[2 * 64 * SSH + 2 * 128 * SSH];
    int e     = blockIdx.z;
    int count = g_counts[e];
    int m0    = blockIdx.y * 64;
    if (m0 >= count) return;
    int n0 = blockIdx.x * 128;

    int tid = threadIdx.x, lane = tid & 31, warp = tid >> 5;
    int wm = (warp >> 1) * 32, wn = (warp & 1) * 64;
    int r = lane >> 2, c = lane & 3;

    float acc[2][8][4] = {};
    down_body<IDIM>(sm,
                    g_act + (size_t)e * T * IDIM + (size_t)(m0 + (tid & 63)) * IDIM,
                    wd + (size_t)e * IDIM * HDIM, n0, acc);

    #pragma unroll
    for (int mt = 0; mt < 2; mt++) {
        int row0 = m0 + wm + mt * 16 + r;
        float w0 = (row0 < count)     ? g_wt[e * T + row0]     : 0.f;
        float w1 = (row0 + 8 < count) ? g_wt[e * T + row0 + 8] : 0.f;
        #pragma unroll
        for (int nt = 0; nt < 8; nt++) {
            int col = n0 + wn + nt * 8 + c * 2;
            if (row0 < count) {
                float2 o = { w0 * acc[mt][nt][0], w0 * acc[mt][nt][1] };
                *(float2*)(g_down + (size_t)(e * T + row0) * HDIM + col) = o;
            }
            if (row0 + 8 < count) {
                float2 o = { w1 * acc[mt][nt][2], w1 * acc[mt][nt][3] };
                *(float2*)(g_down + (size_t)(e * T + row0 + 8) * HDIM + col) = o;
            }
        }
    }
}

__global__ __launch_bounds__(128, 5)
void shared_down_combine_tc(const float* __restrict__ wsd,
                            float* __restrict__ out) {
    __shared__ __align__(16) __half sm[2 * 64 * SSH + 2 * 128 * SSH];
    int m0 = blockIdx.y * 64;
    int n0 = blockIdx.x * 128;

    int tid = threadIdx.x, lane = tid & 31, warp = tid >> 5;
    int wm = (warp >> 1) * 32, wn = (warp & 1) * 64;
    int r = lane >> 2, c = lane & 3;

    float acc[2][8][4] = {};
    down_body<ISDIM>(sm, g_acts + (size_t)(m0 + (tid & 63)) * ISDIM, wsd, n0, acc);

    #pragma unroll
    for (int mt = 0; mt < 2; mt++) {
        #pragma unroll
        for (int half = 0; half < 2; half++) {
            int t = m0 + wm + mt * 16 + r + half * 8;
            float sg = g_sg[t];
            int s0 = g_slot[t * TOPK + 0];
            int s1 = g_slot[t * TOPK + 1];
            int s2 = g_slot[t * TOPK + 2];
            int s3 = g_slot[t * TOPK + 3];
            #pragma unroll
            for (int nt = 0; nt < 8; nt++) {
                int col = n0 + wn + nt * 8 + c * 2;
                float2 d0 = *(const float2*)(g_down + (size_t)s0 * HDIM + col);
                float2 d1 = *(const float2*)(g_down + (size_t)s1 * HDIM + col);
                float2 d2 = *(const float2*)(g_down + (size_t)s2 * HDIM + col);
                float2 d3 = *(const float2*)(g_down + (size_t)s3 * HDIM + col);
                float ax = acc[mt][nt][half * 2 + 0];
                float ay = acc[mt][nt][half * 2 + 1];
                float2 o;
                o.x = sg * ax + d0.x + d1.x + d2.x + d3.x;
                o.y = sg * ay + d0.y + d1.y + d2.y + d3.y;
                *(float2*)(out + (size_t)t * HDIM + col) = o;
            }
        }
    }
}

// ---------------- launch ----------------------------------------------------
extern "C" void kernel_launch(void* const* d_in, const int* in_sizes, int n_in,
                              void* d_out, int out_size) {
    const float* x    = (const float*)d_in[0];
    const float* wr   = (const float*)d_in[1];
    const float* wg   = (const float*)d_in[2];
    const float* wu   = (const float*)d_in[3];
    const float* wd   = (const float*)d_in[4];
    const float* wsg  = (const float*)d_in[5];
    const float* wsu  = (const float*)d_in[6];
    const float* wsd  = (const float*)d_in[7];
    const float* wshg = (const float*)d_in[8];
    float* out = (float*)d_out;

    zero_counts_kernel<<<1, 32>>>();
    router_kernel<<<T, 512>>>(x, wr, wshg, out + (size_t)T * HDIM);
    gateup_expert_tc<<<dim3(IDIM / 64, T / 64, NEXP), 128>>>(x, wg, wu);
    gateup_shared_tc<<<dim3(ISDIM / 64, T / 64), 128>>>(x, wsg, wsu);
    down_expert_tc<<<dim3(HDIM / 128, T / 64, NEXP), 128>>>(wd);
    shared_down_combine_tc<<<dim3(HDIM / 128, T / 64), 128>>>(wsd, out);
}

// round 13
// speedup vs baseline: 1.4013x; 1.4013x over previous
#include <cuda_runtime.h>
#include <cuda_fp16.h>
#include <math.h>

#define T     1024
#define HDIM  1024
#define NEXP  16
#define IDIM  512
#define ISDIM 2048
#define TOPK  4
#define SSH   40        // smem row stride in HALFS (80B rows); BK=32 uses 32 of 40

// ---------------- scratch --------------------------------------------------
__device__ int   g_counts[NEXP];
__device__ int   g_tok[NEXP * T];
__device__ float g_wt[NEXP * T];
__device__ int   g_slot[T * TOPK];
__device__ float g_sg[T];
__device__ float g_act[(size_t)NEXP * T * IDIM];
__device__ float g_acts[(size_t)T * ISDIM];
__device__ float g_down[(size_t)NEXP * T * HDIM];

// ---------------- helpers --------------------------------------------------
__device__ __forceinline__ unsigned pk(float a, float b) {
    __half2 h = __floats2half2_rn(a, b);    // a -> low half (k even), b -> high
    return *(unsigned*)&h;
}
__device__ __forceinline__ unsigned smem_u32(const void* p) {
    return (unsigned)__cvta_generic_to_shared(p);
}
__device__ __forceinline__ void ldsm4(unsigned* d, unsigned addr) {
    asm volatile("ldmatrix.sync.aligned.m8n8.x4.shared.b16 {%0,%1,%2,%3}, [%4];"
                 : "=r"(d[0]), "=r"(d[1]), "=r"(d[2]), "=r"(d[3]) : "r"(addr));
}
__device__ __forceinline__ void mma_f16(float* d, const unsigned* a, const unsigned* b) {
    asm volatile(
        "mma.sync.aligned.m16n8k16.row.col.f32.f16.f16.f32 "
        "{%0,%1,%2,%3}, {%4,%5,%6,%7}, {%8,%9}, {%0,%1,%2,%3};\n"
        : "+f"(d[0]), "+f"(d[1]), "+f"(d[2]), "+f"(d[3])
        : "r"(a[0]), "r"(a[1]), "r"(a[2]), "r"(a[3]), "r"(b[0]), "r"(b[1]));
}
__device__ __forceinline__ float silu(float g) { return g / (1.f + expf(-g)); }

// ---------------- kernel 0: zero counts -------------------------------------
__global__ void zero_counts_kernel() {
    if (threadIdx.x < NEXP) g_counts[threadIdx.x] = 0;
}

// ---------------- kernel 1: router ------------------------------------------
__global__ void router_kernel(const float* __restrict__ x,
                              const float* __restrict__ wr,
                              const float* __restrict__ wsg,
                              float* __restrict__ logits_out) {
    int t    = blockIdx.x;
    int warp = threadIdx.x >> 5;
    int lane = threadIdx.x & 31;
    __shared__ float s_logit[NEXP];

    const float* xr = x + (size_t)t * HDIM;
    {
        float acc = 0.f;
        for (int h = lane; h < HDIM; h += 32)
            acc += xr[h] * wr[h * NEXP + warp];
        #pragma unroll
        for (int o = 16; o; o >>= 1) acc += __shfl_xor_sync(0xffffffffu, acc, o);
        if (lane == 0) { s_logit[warp] = acc; logits_out[t * NEXP + warp] = acc; }
    }
    if (warp == 0) {
        float acc = 0.f;
        for (int h = lane; h < HDIM; h += 32) acc += xr[h] * wsg[h];
        #pragma unroll
        for (int o = 16; o; o >>= 1) acc += __shfl_xor_sync(0xffffffffu, acc, o);
        if (lane == 0) g_sg[t] = 1.f / (1.f + expf(-acc));
    }
    __syncthreads();

    if (threadIdx.x == 0) {
        float p[NEXP];
        float mx = -1e30f;
        #pragma unroll
        for (int e = 0; e < NEXP; e++) mx = fmaxf(mx, s_logit[e]);
        float sum = 0.f;
        #pragma unroll
        for (int e = 0; e < NEXP; e++) { p[e] = expf(s_logit[e] - mx); sum += p[e]; }
        float inv = 1.f / sum;
        #pragma unroll
        for (int e = 0; e < NEXP; e++) p[e] *= inv;

        int idx[TOPK]; float w[TOPK]; float wsum = 0.f;
        #pragma unroll
        for (int k = 0; k < TOPK; k++) {
            int best = 0; float bv = -1.f;
            #pragma unroll
            for (int e = 0; e < NEXP; e++)
                if (p[e] > bv) { bv = p[e]; best = e; }
            idx[k] = best; w[k] = bv; wsum += bv; p[best] = -2.f;
        }
        float winv = 1.f / wsum;
        #pragma unroll
        for (int k = 0; k < TOPK; k++) {
            int e = idx[k];
            int pos = atomicAdd(&g_counts[e], 1);
            g_tok[e * T + pos] = t;
            g_wt[e * T + pos]  = w[k] * winv;
            g_slot[t * TOPK + k] = e * T + pos;
        }
    }
}

// ============================================================================
// gate/up body: BM=64, BN=64, BK=32, 128 thr, warps 2x2 (warp 32x32).
// fp16 m16n8k16; 32 k-halves per smem row (same footprint/banking as BK=16).
// ============================================================================
template<int LDB>
__device__ __forceinline__
void gateup_body(__half* sm, const float* __restrict__ Bgp,
                 const float* __restrict__ Bup,
                 const float* __restrict__ arow0,
                 int count_lim, int m0, int n0, float* __restrict__ Cout) {
    __half* As  = sm;
    __half* Btg = sm + 2 * 64 * SSH;
    __half* Btu = sm + 4 * 64 * SSH;

    int tid = threadIdx.x, lane = tid & 31, warp = tid >> 5;
    int wm = (warp >> 1) * 32, wn = (warp & 1) * 32;
    int r = lane >> 2, c = lane & 3;

    int aoff = (wm + (lane & 7) + ((lane >> 3) & 1) * 8) * SSH + ((lane >> 4) & 1) * 8;
    unsigned aA0 = smem_u32(As) + (unsigned)aoff * 2;
    int boff0 = (wn + (lane & 7) + ((lane >> 4) & 1) * 8) * SSH + ((lane >> 3) & 1) * 8;
    unsigned aBg0 = smem_u32(Btg) + (unsigned)boff0 * 2;
    unsigned aBu0 = smem_u32(Btu) + (unsigned)boff0 * 2;
    const unsigned BUFB = 64 * SSH * 2;

    int arl = tid & 63, akf = (tid >> 6) * 16;          // A: row, 16-k half
    int bnl = tid & 63, bkf = (tid >> 6) * 16;          // B: n, 16-k half

    unsigned sa[8], sg[8], su[8];
    #define GUX_LD(K0) do {                                                    \
        float4 a0 = *(const float4*)(arow0 + (K0) + akf);                      \
        float4 a1 = *(const float4*)(arow0 + (K0) + akf + 4);                  \
        float4 a2 = *(const float4*)(arow0 + (K0) + akf + 8);                  \
        float4 a3 = *(const float4*)(arow0 + (K0) + akf + 12);                 \
        sa[0] = pk(a0.x, a0.y); sa[1] = pk(a0.z, a0.w);                        \
        sa[2] = pk(a1.x, a1.y); sa[3] = pk(a1.z, a1.w);                        \
        sa[4] = pk(a2.x, a2.y); sa[5] = pk(a2.z, a2.w);                        \
        sa[6] = pk(a3.x, a3.y); sa[7] = pk(a3.z, a3.w);                        \
        _Pragma("unroll")                                                      \
        for (int j = 0; j < 8; j++) {                                          \
            float g0 = Bgp[(size_t)((K0) + bkf + 2*j)     * LDB + n0 + bnl];   \
            float g1 = Bgp[(size_t)((K0) + bkf + 2*j + 1) * LDB + n0 + bnl];   \
            sg[j] = pk(g0, g1);                                                \
            float u0 = Bup[(size_t)((K0) + bkf + 2*j)     * LDB + n0 + bnl];   \
            float u1 = Bup[(size_t)((K0) + bkf + 2*j + 1) * LDB + n0 + bnl];   \
            su[j] = pk(u0, u1);                                                \
        }                                                                      \
    } while (0)
    #define GUX_ST(B) do {                                                     \
        *(uint4*)&As [(B) * 64 * SSH + arl * SSH + akf]     = *(uint4*)sa;     \
        *(uint4*)&As [(B) * 64 * SSH + arl * SSH + akf + 8] = *(uint4*)(sa+4); \
        *(uint4*)&Btg[(B) * 64 * SSH + bnl * SSH + bkf]     = *(uint4*)sg;     \
        *(uint4*)&Btg[(B) * 64 * SSH + bnl * SSH + bkf + 8] = *(uint4*)(sg+4); \
        *(uint4*)&Btu[(B) * 64 * SSH + bnl * SSH + bkf]     = *(uint4*)su;     \
        *(uint4*)&Btu[(B) * 64 * SSH + bnl * SSH + bkf + 8] = *(uint4*)(su+4); \
    } while (0)

    float ag[2][4][4] = {};
    float au[2][4][4] = {};

    GUX_LD(0); GUX_ST(0);
    const int NTILES = HDIM / 32;
    for (int kt = 0; kt < NTILES; kt++) {
        __syncthreads();
        if (kt + 1 < NTILES) GUX_LD((kt + 1) * 32);
        unsigned bsel = (kt & 1) * BUFB;
        #pragma unroll
        for (int kb = 0; kb < 2; kb++) {
            unsigned koff = bsel + kb * 32;             // +16 halfs per kb
            unsigned af[2][4], bgf[2][4], buf_[2][4];
            ldsm4(af[0], aA0 + koff);
            ldsm4(af[1], aA0 + koff + 16 * SSH * 2);
            ldsm4(bgf[0], aBg0 + koff);
            ldsm4(bgf[1], aBg0 + koff + 16 * SSH * 2);
            ldsm4(buf_[0], aBu0 + koff);
            ldsm4(buf_[1], aBu0 + koff + 16 * SSH * 2);
            #pragma unroll
            for (int nt = 0; nt < 4; nt++) {
                const unsigned* bg = &bgf[nt >> 1][(nt & 1) * 2];
                const unsigned* bu = &buf_[nt >> 1][(nt & 1) * 2];
                #pragma unroll
                for (int mt = 0; mt < 2; mt++) {
                    mma_f16(ag[mt][nt], af[mt], bg);
                    mma_f16(au[mt][nt], af[mt], bu);
                }
            }
        }
        if (kt + 1 < NTILES) GUX_ST((kt + 1) & 1);
    }

    #pragma unroll
    for (int mt = 0; mt < 2; mt++) {
        int row0 = m0 + wm + mt * 16 + r;
        #pragma unroll
        for (int nt = 0; nt < 4; nt++) {
            int col = n0 + wn + nt * 8 + c * 2;
            if (row0 < count_lim) {
                float2 o = { silu(ag[mt][nt][0]) * au[mt][nt][0],
                             silu(ag[mt][nt][1]) * au[mt][nt][1] };
                *(float2*)(Cout + (size_t)row0 * LDB + col) = o;
            }
            if (row0 + 8 < count_lim) {
                float2 o = { silu(ag[mt][nt][2]) * au[mt][nt][2],
                             silu(ag[mt][nt][3]) * au[mt][nt][3] };
                *(float2*)(Cout + (size_t)(row0 + 8) * LDB + col) = o;
            }
        }
    }
}

__global__ __launch_bounds__(128)
void gateup_expert_tc(const float* __restrict__ x,
                      const float* __restrict__ wg,
                      const float* __restrict__ wu) {
    __shared__ __align__(16) __half sm[6 * 64 * SSH];
    int e     = blockIdx.z;
    int count = g_counts[e];
    int m0    = blockIdx.y * 64;
    if (m0 >= count) return;
    int row = m0 + (threadIdx.x & 63);
    int tok = (row < count) ? g_tok[e * T + row] : 0;   // guarded at store
    gateup_body<IDIM>(sm, wg + (size_t)e * HDIM * IDIM,
                      wu + (size_t)e * HDIM * IDIM,
                      x + (size_t)tok * HDIM, count, m0, blockIdx.x * 64,
                      g_act + (size_t)e * T * IDIM);
}

__global__ __launch_bounds__(128)
void gateup_shared_tc(const float* __restrict__ x,
                      const float* __restrict__ wsg,
                      const float* __restrict__ wsu) {
    __shared__ __align__(16) __half sm[6 * 64 * SSH];
    int m0 = blockIdx.y * 64;
    gateup_body<ISDIM>(sm, wsg, wsu,
                       x + (size_t)(m0 + (threadIdx.x & 63)) * HDIM,
                       T, m0, blockIdx.x * 64, g_acts);
}

// ============================================================================
// down body: BM=64, BN=128, BK=32, 128 thr, warps 2x2 (warp 32x64).
// ============================================================================
template<int KDIM>
__device__ __forceinline__
void down_body(__half* sm, const float* __restrict__ arow0,
               const float* __restrict__ Bp, int n0, float acc[2][8][4]) {
    __half* As = sm;
    __half* Bt = sm + 2 * 64 * SSH;

    int tid = threadIdx.x, lane = tid & 31, warp = tid >> 5;
    int wm = (warp >> 1) * 32, wn = (warp & 1) * 64;

    int aoff = (wm + (lane & 7) + ((lane >> 3) & 1) * 8) * SSH + ((lane >> 4) & 1) * 8;
    unsigned aA0 = smem_u32(As) + (unsigned)aoff * 2;
    int boff0 = (wn + (lane & 7) + ((lane >> 4) & 1) * 8) * SSH + ((lane >> 3) & 1) * 8;
    unsigned aB0 = smem_u32(Bt) + (unsigned)boff0 * 2;
    const unsigned ABUF = 64 * SSH * 2, BBUF = 128 * SSH * 2;

    int arl = tid & 63, akf = (tid >> 6) * 16;
    int bnl = tid;                                      // n = 0..127, all 32 k's

    unsigned sa[8], sb[16];
    #define DNX_LD(K0) do {                                                    \
        float4 a0 = *(const float4*)(arow0 + (K0) + akf);                      \
        float4 a1 = *(const float4*)(arow0 + (K0) + akf + 4);                  \
        float4 a2 = *(const float4*)(arow0 + (K0) + akf + 8);                  \
        float4 a3 = *(const float4*)(arow0 + (K0) + akf + 12);                 \
        sa[0] = pk(a0.x, a0.y); sa[1] = pk(a0.z, a0.w);                        \
        sa[2] = pk(a1.x, a1.y); sa[3] = pk(a1.z, a1.w);                        \
        sa[4] = pk(a2.x, a2.y); sa[5] = pk(a2.z, a2.w);                        \
        sa[6] = pk(a3.x, a3.y); sa[7] = pk(a3.z, a3.w);                        \
        _Pragma("unroll")                                                      \
        for (int j = 0; j < 16; j++) {                                         \
            float b0 = Bp[(size_t)((K0) + 2*j)     * HDIM + n0 + bnl];         \
            float b1 = Bp[(size_t)((K0) + 2*j + 1) * HDIM + n0 + bnl];         \
            sb[j] = pk(b0, b1);                                                \
        }                                                                      \
    } while (0)
    #define DNX_ST(B) do {                                                     \
        *(uint4*)&As[(B) * 64 * SSH + arl * SSH + akf]     = *(uint4*)sa;      \
        *(uint4*)&As[(B) * 64 * SSH + arl * SSH + akf + 8] = *(uint4*)(sa+4);  \
        *(uint4*)&Bt[(B) * 128 * SSH + bnl * SSH]      = *(uint4*)sb;          \
        *(uint4*)&Bt[(B) * 128 * SSH + bnl * SSH + 8]  = *(uint4*)(sb + 4);    \
        *(uint4*)&Bt[(B) * 128 * SSH + bnl * SSH + 16] = *(uint4*)(sb + 8);    \
        *(uint4*)&Bt[(B) * 128 * SSH + bnl * SSH + 24] = *(uint4*)(sb + 12);   \
    } while (0)

    DNX_LD(0); DNX_ST(0);
    const int NTILES = KDIM / 32;
    for (int kt = 0; kt < NTILES; kt++) {
        __syncthreads();
        if (kt + 1 < NTILES) DNX_LD((kt + 1) * 32);
        unsigned bselA = (kt & 1) * ABUF, bselB = (kt & 1) * BBUF;
        #pragma unroll
        for (int kb = 0; kb < 2; kb++) {
            unsigned af[2][4], bf[4][4];
            ldsm4(af[0], aA0 + bselA + kb * 32);
            ldsm4(af[1], aA0 + bselA + kb * 32 + 16 * SSH * 2);
            #pragma unroll
            for (int p = 0; p < 4; p++)
                ldsm4(bf[p], aB0 + bselB + kb * 32 + p * 16 * SSH * 2);
            #pragma unroll
            for (int nt = 0; nt < 8; nt++) {
                const unsigned* b = &bf[nt >> 1][(nt & 1) * 2];
                #pragma unroll
                for (int mt = 0; mt < 2; mt++)
                    mma_f16(acc[mt][nt], af[mt], b);
            }
        }
        if (kt + 1 < NTILES) DNX_ST((kt + 1) & 1);
    }
}

__global__ __launch_bounds__(128)
void down_expert_tc(const float* __restrict__ wd) {
    __shared__ __align__(16) __half sm[2 * 64 * SSH + 2 * 128 * SSH];
    int e     = blockIdx.z;
    int count = g_counts[e];
    int m0    = blockIdx.y * 64;
    if (m0 >= count) return;
    int n0 = blockIdx.x * 128;

    int tid = threadIdx.x, lane = tid & 31, warp = tid >> 5;
    int wm = (warp >> 1) * 32, wn = (warp & 1) * 64;
    int r = lane >> 2, c = lane & 3;

    float acc[2][8][4] = {};
    down_body<IDIM>(sm,
                    g_act + (size_t)e * T * IDIM + (size_t)(m0 + (tid & 63)) * IDIM,
                    wd + (size_t)e * IDIM * HDIM, n0, acc);

    #pragma unroll
    for (int mt = 0; mt < 2; mt++) {
        int row0 = m0 + wm + mt * 16 + r;
        float w0 = (row0 < count)     ? g_wt[e * T + row0]     : 0.f;
        float w1 = (row0 + 8 < count) ? g_wt[e * T + row0 + 8] : 0.f;
        #pragma unroll
        for (int nt = 0; nt < 8; nt++) {
            int col = n0 + wn + nt * 8 + c * 2;
            if (row0 < count) {
                float2 o = { w0 * acc[mt][nt][0], w0 * acc[mt][nt][1] };
                *(float2*)(g_down + (size_t)(e * T + row0) * HDIM + col) = o;
            }
            if (row0 + 8 < count) {
                float2 o = { w1 * acc[mt][nt][2], w1 * acc[mt][nt][3] };
                *(float2*)(g_down + (size_t)(e * T + row0 + 8) * HDIM + col) = o;
            }
        }
    }
}

__global__ __launch_bounds__(128)
void shared_down_combine_tc(const float* __restrict__ wsd,
                            float* __restrict__ out) {
    __shared__ __align__(16) __half sm[2 * 64 * SSH + 2 * 128 * SSH];
    int m0 = blockIdx.y * 64;
    int n0 = blockIdx.x * 128;

    int tid = threadIdx.x, lane = tid & 31, warp = tid >> 5;
    int wm = (warp >> 1) * 32, wn = (warp & 1) * 64;
    int r = lane >> 2, c = lane & 3;

    float acc[2][8][4] = {};
    down_body<ISDIM>(sm, g_acts + (size_t)(m0 + (tid & 63)) * ISDIM, wsd, n0, acc);

    #pragma unroll
    for (int mt = 0; mt < 2; mt++) {
        #pragma unroll
        for (int half = 0; half < 2; half++) {
            int t = m0 + wm + mt * 16 + r + half * 8;
            float sg = g_sg[t];
            int s0 = g_slot[t * TOPK + 0];
            int s1 = g_slot[t * TOPK + 1];
            int s2 = g_slot[t * TOPK + 2];
            int s3 = g_slot[t * TOPK + 3];
            #pragma unroll
            for (int nt = 0; nt < 8; nt++) {
                int col = n0 + wn + nt * 8 + c * 2;
                float2 d0 = *(const float2*)(g_down + (size_t)s0 * HDIM + col);
                float2 d1 = *(const float2*)(g_down + (size_t)s1 * HDIM + col);
                float2 d2 = *(const float2*)(g_down + (size_t)s2 * HDIM + col);
                float2 d3 = *(const float2*)(g_down + (size_t)s3 * HDIM + col);
                float ax = acc[mt][nt][half * 2 + 0];
                float ay = acc[mt][nt][half * 2 + 1];
                float2 o;
                o.x = sg * ax + d0.x + d1.x + d2.x + d3.x;
                o.y = sg * ay + d0.y + d1.y + d2.y + d3.y;
                *(float2*)(out + (size_t)t * HDIM + col) = o;
            }
        }
    }
}

// ---------------- launch ----------------------------------------------------
extern "C" void kernel_launch(void* const* d_in, const int* in_sizes, int n_in,
                              void* d_out, int out_size) {
    const float* x    = (const float*)d_in[0];
    const float* wr   = (const float*)d_in[1];
    const float* wg   = (const float*)d_in[2];
    const float* wu   = (const float*)d_in[3];
    const float* wd   = (const float*)d_in[4];
    const float* wsg  = (const float*)d_in[5];
    const float* wsu  = (const float*)d_in[6];
    const float* wsd  = (const float*)d_in[7];
    const float* wshg = (const float*)d_in[8];
    float* out = (float*)d_out;

    zero_counts_kernel<<<1, 32>>>();
    router_kernel<<<T, 512>>>(x, wr, wshg, out + (size_t)T * HDIM);
    gateup_expert_tc<<<dim3(IDIM / 64, T / 64, NEXP), 128>>>(x, wg, wu);
    gateup_shared_tc<<<dim3(ISDIM / 64, T / 64), 128>>>(x, wsg, wsu);
    down_expert_tc<<<dim3(HDIM / 128, T / 64, NEXP), 128>>>(wd);
    shared_down_combine_tc<<<dim3(HDIM / 128, T / 64), 128>>>(wsd, out);
}